// round 10
// baseline (speedup 1.0000x reference)
#include <cuda_runtime.h>
#include <cstdint>

#define NN 8192
#define KB 4096               // histogram buckets (fine sort -> tight bounds)
#define NCHUNK 256            // 256 chunks of 32 sorted candidates

// Scratch (device globals — no allocation allowed in kernel_launch).
// Zero-initialized at load; every array is re-established each launch chain.
__device__ float    g_s[NN];          // s[j] by original index
__device__ float    g_wm[NN];         // wmax[j] by original index
__device__ int      g_bk[NN];         // bucket id by original index
__device__ __align__(16) int g_hist[KB];  // histogram (re-zeroed by scan for next run)
__device__ __align__(16) int g_cur[KB];   // exclusive offsets -> scatter cursors
__device__ float    g_ss[NN];         // s in bucket-sorted order
__device__ float    g_ws[NN];         // wmax in bucket-sorted order
__device__ int      g_idx[NN];        // original index in bucket-sorted order
__device__ unsigned g_csmin[NCHUNK];  // per-chunk min s   (positive-float bits, atomicMin)
__device__ unsigned g_cwmax[NCHUNK];  // per-chunk max w   (positive-float bits, atomicMax)
__device__ unsigned g_cnsmin[NCHUNK]; // per-chunk max -s*w (negative-float bits, atomicMin)

// K1: per-element s, wmax, bucket; histogram via spread global atomics
__global__ __launch_bounds__(128)
void bucket_kernel(const float* __restrict__ x, const float* __restrict__ Wphi) {
    int j = blockIdx.x * 128 + threadIdx.x;
    float s = x[3 * j + 0] + x[3 * j + 1] + x[3 * j + 2];
    float w0 = Wphi[j], w1 = Wphi[NN + j], w2 = Wphi[2 * NN + j];
    float w = fmaxf(w0, fmaxf(w1, w2));
    int b = (int)(s * (KB / 3.0f));
    b = max(0, min(KB - 1, b));
    g_s[j]  = s;
    g_wm[j] = w;
    g_bk[j] = b;
    atomicAdd(&g_hist[b], 1);
}

// K2: exclusive scan hist -> cur; zero hist for next replay; init chunk stats
__global__ __launch_bounds__(1024)
void scan_kernel() {
    __shared__ int warpsums[32];
    const int t = threadIdx.x, lane = t & 31, wid = t >> 5;

    int4 h = reinterpret_cast<const int4*>(g_hist)[t];           // buckets 4t..4t+3
    reinterpret_cast<int4*>(g_hist)[t] = make_int4(0, 0, 0, 0);  // ready for next run

    int lsum = h.x + h.y + h.z + h.w;
    int inc = lsum;
    #pragma unroll
    for (int off = 1; off < 32; off <<= 1) {
        int n = __shfl_up_sync(0xffffffffu, inc, off);
        if (lane >= off) inc += n;
    }
    if (lane == 31) warpsums[wid] = inc;
    __syncthreads();
    if (wid == 0) {
        int ws = warpsums[lane];
        int winc = ws;
        #pragma unroll
        for (int off = 1; off < 32; off <<= 1) {
            int n = __shfl_up_sync(0xffffffffu, winc, off);
            if (lane >= off) winc += n;
        }
        warpsums[lane] = winc - ws;   // exclusive warp offset
    }
    __syncthreads();
    int base = warpsums[wid] + (inc - lsum);
    int4 o;
    o.x = base;
    o.y = base + h.x;
    o.z = base + h.x + h.y;
    o.w = base + h.x + h.y + h.z;
    reinterpret_cast<int4*>(g_cur)[t] = o;

    if (t < NCHUNK) {
        g_csmin[t]  = 0x7F800000u;   // +inf
        g_cwmax[t]  = 0u;            // 0.0f (all w > 0)
        g_cnsmin[t] = 0xFFFFFFFFu;   // most-negative float bits
    }
}

// K3: scatter into sorted arrays; fold per-chunk stats in via bitwise atomics.
// s>0 and w>0 -> int bits monotone; -s*w<=0 -> uint bits reverse-monotone.
__global__ __launch_bounds__(128)
void scatter_kernel() {
    int j = blockIdx.x * 128 + threadIdx.x;
    float s = g_s[j];
    float w = g_wm[j];
    int pos = atomicAdd(&g_cur[g_bk[j]], 1);
    g_ss[pos]  = s;
    g_ws[pos]  = w;
    g_idx[pos] = j;
    int c = pos >> 5;
    atomicMin(&g_csmin[c],  __float_as_uint(s));
    atomicMax(&g_cwmax[c],  __float_as_uint(w));
    atomicMin(&g_cnsmin[c], __float_as_uint(-s * w));   // uint-min == float-max (negatives)
}

// K4: warp per row — 6-deep gated prefetch pipeline over 32-candidate chunks.
__global__ __launch_bounds__(256)
void probe_kernel(const int* __restrict__ adj, float* __restrict__ out) {
    __shared__ float s_cmin[NCHUNK], s_cwub[NCHUNK], s_cnsw[NCHUNK];

    const int t = threadIdx.x;
    const int lane = t & 31;
    const int warp = t >> 5;

    // Load raw chunk stats (hot L2) into smem
    s_cmin[t] = __uint_as_float(g_csmin[t]);
    s_cwub[t] = __uint_as_float(g_cwmax[t]);
    s_cnsw[t] = __uint_as_float(g_cnsmin[t]);
    __syncthreads();

    // Warp 0: in-place suffix scan over 256 chunks (8 per lane)
    if (t < 32) {
        float lm[8], lw[8], ln[8];
        float amn = 3.0e38f, amx = -3.0e38f, ans = -3.0e38f;
        #pragma unroll
        for (int q = 0; q < 8; q++) {
            lm[q] = s_cmin[t * 8 + q];
            lw[q] = s_cwub[t * 8 + q];
            ln[q] = s_cnsw[t * 8 + q];
            amn = fminf(amn, lm[q]);
            amx = fmaxf(amx, lw[q]);
            ans = fmaxf(ans, ln[q]);
        }
        float smn = amn, smx = amx, sns = ans;
        #pragma unroll
        for (int off = 1; off < 32; off <<= 1) {
            float a = __shfl_down_sync(0xffffffffu, smn, off);
            float b = __shfl_down_sync(0xffffffffu, smx, off);
            float c = __shfl_down_sync(0xffffffffu, sns, off);
            if (lane + off < 32) {
                smn = fminf(smn, a); smx = fmaxf(smx, b); sns = fmaxf(sns, c);
            }
        }
        float tmn = __shfl_down_sync(0xffffffffu, smn, 1);
        float tmx = __shfl_down_sync(0xffffffffu, smx, 1);
        float tns = __shfl_down_sync(0xffffffffu, sns, 1);
        if (lane == 31) { tmn = 3.0e38f; tmx = -3.0e38f; tns = -3.0e38f; }
        float rmn = tmn, rmx = tmx, rns = tns;
        #pragma unroll
        for (int q = 7; q >= 0; q--) {
            rmn = fminf(rmn, lm[q]);
            rmx = fmaxf(rmx, lw[q]);
            rns = fmaxf(rns, ln[q]);
            s_cmin[t * 8 + q] = rmn;
            s_cwub[t * 8 + q] = rmx;
            s_cnsw[t * 8 + q] = rns;
        }
    }
    __syncthreads();

    const int i = blockIdx.x * 8 + warp;
    const float si = g_s[i];
    const int* __restrict__ arow = adj + (size_t)i * NN;

    float lbest = 0.0f;   // per-lane running max; reference includes T[i,i]=0
    int a0, a1, a2, a3 = 0, a4 = 0, a5 = 0;

    // Ungated issue of chunks 0..2
    a0 = __ldg(&arow[g_idx[0 * 32 + lane]]);
    a1 = __ldg(&arow[g_idx[1 * 32 + lane]]);
    a2 = __ldg(&arow[g_idx[2 * 32 + lane]]);

    // Process chunk 0 first so the gates below see a realistic best
    {
        float d = si - g_ss[lane];
        if (d > 0.0f && a0) lbest = d * g_ws[lane];
    }

    int  last = 2;        // last issued chunk (warp-uniform)
    bool stop = false;    // gate latch (warp-uniform; bounds are monotone)

    // Gated fill of chunks 3..5
    #pragma unroll
    for (int k = 3; k <= 5; k++) {
        if (!stop) {
            float b1 = (si - s_cmin[k]) * s_cwub[k];
            float b2 = si * s_cwub[k] + s_cnsw[k] + 1e-5f;
            if (__any_sync(0xffffffffu, lbest >= fminf(b1, b2))) {
                stop = true;
            } else {
                int v = __ldg(&arow[g_idx[k * 32 + lane]]);
                if (k == 3) a3 = v; else if (k == 4) a4 = v; else a5 = v;
                last = k;
            }
        }
    }

    // Main pipeline: chunk c lives in slot c%6. Chunk 0 reprocessed (idempotent).
    for (int cc = 0; cc < NCHUNK; cc += 6) {
        #pragma unroll
        for (int q = 0; q < 6; q++) {
            const int c = cc + q;
            if (c > last) goto done_scan;                 // warp-uniform

            int av = (q == 0) ? a0 : (q == 1) ? a1 : (q == 2) ? a2
                   : (q == 3) ? a3 : (q == 4) ? a4 : a5;
            const int k = c * 32 + lane;
            float d = si - g_ss[k];
            if (d > 0.0f && av) lbest = fmaxf(lbest, d * g_ws[k]);

            const int nxt = c + 6;                        // reuses slot q
            if (!stop && nxt < NCHUNK) {
                float b1 = (si - s_cmin[nxt]) * s_cwub[nxt];
                float b2 = si * s_cwub[nxt] + s_cnsw[nxt] + 1e-5f;
                if (__any_sync(0xffffffffu, lbest >= fminf(b1, b2))) {
                    stop = true;
                } else {
                    int v = __ldg(&arow[g_idx[nxt * 32 + lane]]);
                    if (q == 0) a0 = v; else if (q == 1) a1 = v;
                    else if (q == 2) a2 = v; else if (q == 3) a3 = v;
                    else if (q == 4) a4 = v; else a5 = v;
                    last = nxt;
                }
            }
        }
    }
done_scan:

    // Final warp max-reduce
    float best = lbest;
    #pragma unroll
    for (int off = 16; off; off >>= 1)
        best = fmaxf(best, __shfl_xor_sync(0xffffffffu, best, off));

    if (lane == 0) {
        out[i * 3 + 0] = best;
        out[i * 3 + 1] = best;
        out[i * 3 + 2] = best;
    }
}

extern "C" void kernel_launch(void* const* d_in, const int* in_sizes, int n_in,
                              void* d_out, int out_size) {
    const float* x    = (const float*)d_in[0];
    const int*   adj  = (const int*)d_in[1];
    const float* Wphi = (const float*)d_in[2];
    // d_in[3] (W_theta) is unused in the forward pass.
    float* out = (float*)d_out;

    bucket_kernel<<<NN / 128, 128>>>(x, Wphi);
    scan_kernel<<<1, 1024>>>();
    scatter_kernel<<<NN / 128, 128>>>();
    probe_kernel<<<NN / 8, 256>>>(adj, out);
}